// round 1
// baseline (speedup 1.0000x reference)
#include <cuda_runtime.h>
#include <math.h>

#define CC 192
#define NB1 4096
#define NB2 1024

// ---------------- scratch (device globals; no allocation) ----------------
__device__ float d_freq[48];
__device__ float g_xn[4 * NB1 * CC];      // stage1 nodes
__device__ float g_nb[4 * NB1 * CC];      // neighbor means (reused stage2)
__device__ float g_sage[4 * NB1 * CC];    // sage1 out
__device__ float g_pool[4 * NB2 * CC];    // pooled1
__device__ float g_gdn[4 * NB2 * CC];     // gdn out = stage2 nodes
__device__ float g_sage2[4 * NB2 * CC];   // sage2 out
__device__ float g_pool2[4 * 256 * CC];   // pooled2
__device__ float g_sqn[4 * NB1];
__device__ int   g_idx[4 * NB1 * 9];
__device__ int   g_perm[4 * NB2];
__device__ float g_sv[4 * NB2];
__device__ float g_scores[4 * NB1];
__device__ float g_scal[2];

// ---------------- positional-encoding frequency table ----------------
__global__ void k_freq() {
    int j = threadIdx.x;
    if (j < 48) d_freq[j] = (float)(1.0 / pow(10000.0, (double)(2 * j) / 96.0));
}

// ---------------- add pos-enc, build node features + sq norms ----------------
__global__ void k_prep(const float* __restrict__ x, float* __restrict__ xn,
                       float* __restrict__ sqn) {
    int n = blockIdx.x, b = blockIdx.y, c = threadIdx.x;
    int y = n >> 6, xw = n & 63;
    float v = x[(((size_t)b * CC + c) * 64 + y) * 64 + xw];
    float f, arg;
    if (c < 96) { f = d_freq[c >> 1];        arg = (float)y  * f; }
    else        { f = d_freq[(c - 96) >> 1]; arg = (float)xw * f; }
    v += (c & 1) ? cosf(arg) : sinf(arg);
    xn[((size_t)b * NB1 + n) * CC + c] = v;

    __shared__ float red[192];
    red[c] = v * v;
    __syncthreads();
    if (c < 64) red[c] += red[c + 64] + red[c + 128];
    __syncthreads();
    if (c < 32) {
        float s = red[c] + red[c + 32];
        for (int o = 16; o; o >>= 1) s += __shfl_down_sync(0xffffffffu, s, o);
        if (c == 0) sqn[b * NB1 + n] = s;
    }
}

// ---------------- generic squared-norm kernel ----------------
__global__ void k_sqn(const float* __restrict__ xn, float* __restrict__ sqn, int N) {
    int n = blockIdx.x, b = blockIdx.y, c = threadIdx.x;
    float v = xn[((size_t)b * N + n) * CC + c];
    __shared__ float red[192];
    red[c] = v * v;
    __syncthreads();
    if (c < 64) red[c] += red[c + 64] + red[c + 128];
    __syncthreads();
    if (c < 32) {
        float s = red[c] + red[c + 32];
        for (int o = 16; o; o >>= 1) s += __shfl_down_sync(0xffffffffu, s, o);
        if (c == 0) sqn[b * N + n] = s;
    }
}

// ---------------- fused distance-GEMM + running top-9 ----------------
// block: 256 threads (16x16, 4x4 microtile), tile 64 rows x 64 cols, K chunk 16.
__global__ void k_knn(const float* __restrict__ xn, const float* __restrict__ sqn,
                      int* __restrict__ idxOut, int N) {
    int b = blockIdx.y;
    int rowBase = blockIdx.x << 6;
    const float* X  = xn  + (size_t)b * N * CC;
    const float* SQ = sqn + (size_t)b * N;

    __shared__ __align__(16) float As[16][68];
    __shared__ __align__(16) float Bs[16][68];
    __shared__ float Ds[64][65];

    int tid = threadIdx.x;
    int ty = tid >> 4, tx = tid & 15;
    int lr = tid >> 2, lk = (tid & 3) << 2;

    float hd[9]; int hi[9];
#pragma unroll
    for (int q = 0; q < 9; q++) { hd[q] = 3.4e38f; hi[q] = 0; }

    float sr[4];
#pragma unroll
    for (int i = 0; i < 4; i++) sr[i] = SQ[rowBase + (ty << 2) + i];

    for (int colBase = 0; colBase < N; colBase += 64) {
        float acc[4][4] = {};
        for (int kk = 0; kk < 192; kk += 16) {
            float4 av = *(const float4*)(X + (size_t)(rowBase + lr) * CC + kk + lk);
            float4 bv = *(const float4*)(X + (size_t)(colBase + lr) * CC + kk + lk);
            __syncthreads();
            As[lk + 0][lr] = av.x; As[lk + 1][lr] = av.y;
            As[lk + 2][lr] = av.z; As[lk + 3][lr] = av.w;
            Bs[lk + 0][lr] = bv.x; Bs[lk + 1][lr] = bv.y;
            Bs[lk + 2][lr] = bv.z; Bs[lk + 3][lr] = bv.w;
            __syncthreads();
#pragma unroll
            for (int k = 0; k < 16; k++) {
                float4 a  = *(const float4*)&As[k][ty << 2];
                float4 bq = *(const float4*)&Bs[k][tx << 2];
                acc[0][0] += a.x * bq.x; acc[0][1] += a.x * bq.y;
                acc[0][2] += a.x * bq.z; acc[0][3] += a.x * bq.w;
                acc[1][0] += a.y * bq.x; acc[1][1] += a.y * bq.y;
                acc[1][2] += a.y * bq.z; acc[1][3] += a.y * bq.w;
                acc[2][0] += a.z * bq.x; acc[2][1] += a.z * bq.y;
                acc[2][2] += a.z * bq.z; acc[2][3] += a.z * bq.w;
                acc[3][0] += a.w * bq.x; acc[3][1] += a.w * bq.y;
                acc[3][2] += a.w * bq.z; acc[3][3] += a.w * bq.w;
            }
        }
#pragma unroll
        for (int i = 0; i < 4; i++)
#pragma unroll
            for (int j = 0; j < 4; j++) {
                float sc = SQ[colBase + (tx << 2) + j];
                Ds[(ty << 2) + i][(tx << 2) + j] = fmaf(-2.f, acc[i][j], sr[i] + sc);
            }
        __syncthreads();
        if (tid < 64) {
#pragma unroll 1
            for (int c2 = 0; c2 < 64; c2++) {
                float dval = Ds[tid][c2];
                if (dval < hd[8]) {            // strict <: jax tie-break (earlier idx wins)
                    hd[8] = dval; hi[8] = colBase + c2;
#pragma unroll
                    for (int q = 8; q > 0; q--) {
                        if (hd[q - 1] > dval) {
                            float td = hd[q - 1]; hd[q - 1] = hd[q]; hd[q] = td;
                            int   ti = hi[q - 1]; hi[q - 1] = hi[q]; hi[q] = ti;
                        } else break;
                    }
                }
            }
        }
        __syncthreads();
    }
    if (tid < 64) {
        size_t base = ((size_t)b * N + rowBase + tid) * 9;
#pragma unroll
        for (int q = 0; q < 9; q++) idxOut[base + q] = hi[q];
    }
}

// ---------------- gather + mean over 9 neighbors ----------------
__global__ void k_gather(const float* __restrict__ xn, const int* __restrict__ idx,
                         float* __restrict__ out, int N) {
    __shared__ int sid[9];
    int n = blockIdx.x, b = blockIdx.y, c = threadIdx.x;
    if (c < 9) sid[c] = idx[((size_t)b * N + n) * 9 + c];
    __syncthreads();
    const float* X = xn + (size_t)b * N * CC;
    float s = 0.f;
#pragma unroll
    for (int k = 0; k < 9; k++) s += X[(size_t)sid[k] * CC + c];
    out[((size_t)b * N + n) * CC + c] = s / 9.0f;
}

// ---------------- SAGE: out = A1 @ W1^T + A2 @ W2^T + bias ----------------
__global__ void k_sage(const float* __restrict__ A1, const float* __restrict__ A2,
                       const float* __restrict__ W1, const float* __restrict__ W2,
                       const float* __restrict__ bias, float* __restrict__ out) {
    int rowBase = blockIdx.x << 6;
    int oBase   = blockIdx.y << 6;
    __shared__ __align__(16) float A1s[16][68], A2s[16][68], W1s[16][68], W2s[16][68];
    int tid = threadIdx.x, ty = tid >> 4, tx = tid & 15;
    int lr = tid >> 2, lk = (tid & 3) << 2;
    float acc[4][4] = {};
    for (int kk = 0; kk < 192; kk += 16) {
        float4 a1 = *(const float4*)(A1 + (size_t)(rowBase + lr) * CC + kk + lk);
        float4 a2 = *(const float4*)(A2 + (size_t)(rowBase + lr) * CC + kk + lk);
        float4 w1 = *(const float4*)(W1 + (size_t)(oBase + lr) * CC + kk + lk);
        float4 w2 = *(const float4*)(W2 + (size_t)(oBase + lr) * CC + kk + lk);
        __syncthreads();
        A1s[lk+0][lr]=a1.x; A1s[lk+1][lr]=a1.y; A1s[lk+2][lr]=a1.z; A1s[lk+3][lr]=a1.w;
        A2s[lk+0][lr]=a2.x; A2s[lk+1][lr]=a2.y; A2s[lk+2][lr]=a2.z; A2s[lk+3][lr]=a2.w;
        W1s[lk+0][lr]=w1.x; W1s[lk+1][lr]=w1.y; W1s[lk+2][lr]=w1.z; W1s[lk+3][lr]=w1.w;
        W2s[lk+0][lr]=w2.x; W2s[lk+1][lr]=w2.y; W2s[lk+2][lr]=w2.z; W2s[lk+3][lr]=w2.w;
        __syncthreads();
#pragma unroll
        for (int k = 0; k < 16; k++) {
            float4 xa = *(const float4*)&A1s[k][ty << 2];
            float4 xb = *(const float4*)&A2s[k][ty << 2];
            float4 u  = *(const float4*)&W1s[k][tx << 2];
            float4 v  = *(const float4*)&W2s[k][tx << 2];
            acc[0][0] += xa.x*u.x + xb.x*v.x; acc[0][1] += xa.x*u.y + xb.x*v.y;
            acc[0][2] += xa.x*u.z + xb.x*v.z; acc[0][3] += xa.x*u.w + xb.x*v.w;
            acc[1][0] += xa.y*u.x + xb.y*v.x; acc[1][1] += xa.y*u.y + xb.y*v.y;
            acc[1][2] += xa.y*u.z + xb.y*v.z; acc[1][3] += xa.y*u.w + xb.y*v.w;
            acc[2][0] += xa.z*u.x + xb.z*v.x; acc[2][1] += xa.z*u.y + xb.z*v.y;
            acc[2][2] += xa.z*u.z + xb.z*v.z; acc[2][3] += xa.z*u.w + xb.z*v.w;
            acc[3][0] += xa.w*u.x + xb.w*v.x; acc[3][1] += xa.w*u.y + xb.w*v.y;
            acc[3][2] += xa.w*u.z + xb.w*v.z; acc[3][3] += xa.w*u.w + xb.w*v.w;
        }
    }
#pragma unroll
    for (int i = 0; i < 4; i++)
#pragma unroll
        for (int j = 0; j < 4; j++) {
            int oc = oBase + (tx << 2) + j;
            out[(size_t)(rowBase + (ty << 2) + i) * CC + oc] = acc[i][j] + bias[oc];
        }
}

// ---------------- GDN: y = x * rsqrt(x^2 @ gamma^T + beta) ----------------
__global__ void k_gdn(const float* __restrict__ X, const float* __restrict__ gamma,
                      const float* __restrict__ beta, float* __restrict__ out) {
    int rowBase = blockIdx.x << 6;
    int oBase   = blockIdx.y << 6;
    __shared__ __align__(16) float As[16][68], Gs[16][68];
    int tid = threadIdx.x, ty = tid >> 4, tx = tid & 15;
    int lr = tid >> 2, lk = (tid & 3) << 2;
    float acc[4][4] = {};
    for (int kk = 0; kk < 192; kk += 16) {
        float4 a = *(const float4*)(X     + (size_t)(rowBase + lr) * CC + kk + lk);
        float4 g = *(const float4*)(gamma + (size_t)(oBase + lr) * CC + kk + lk);
        __syncthreads();
        As[lk+0][lr]=a.x*a.x; As[lk+1][lr]=a.y*a.y; As[lk+2][lr]=a.z*a.z; As[lk+3][lr]=a.w*a.w;
        Gs[lk+0][lr]=g.x; Gs[lk+1][lr]=g.y; Gs[lk+2][lr]=g.z; Gs[lk+3][lr]=g.w;
        __syncthreads();
#pragma unroll
        for (int k = 0; k < 16; k++) {
            float4 xa = *(const float4*)&As[k][ty << 2];
            float4 u  = *(const float4*)&Gs[k][tx << 2];
            acc[0][0]+=xa.x*u.x; acc[0][1]+=xa.x*u.y; acc[0][2]+=xa.x*u.z; acc[0][3]+=xa.x*u.w;
            acc[1][0]+=xa.y*u.x; acc[1][1]+=xa.y*u.y; acc[1][2]+=xa.y*u.z; acc[1][3]+=xa.y*u.w;
            acc[2][0]+=xa.z*u.x; acc[2][1]+=xa.z*u.y; acc[2][2]+=xa.z*u.z; acc[2][3]+=xa.z*u.w;
            acc[3][0]+=xa.w*u.x; acc[3][1]+=xa.w*u.y; acc[3][2]+=xa.w*u.z; acc[3][3]+=xa.w*u.w;
        }
    }
#pragma unroll
    for (int i = 0; i < 4; i++)
#pragma unroll
        for (int j = 0; j < 4; j++) {
            int oc = oBase + (tx << 2) + j;
            size_t off = (size_t)(rowBase + (ty << 2) + i) * CC + oc;
            float xv = X[off];
            out[off] = xv * rsqrtf(acc[i][j] + beta[oc]);
        }
}

// ---------------- ||w|| ----------------
__global__ void k_wnorm(const float* __restrict__ w, float* __restrict__ outp) {
    int c = threadIdx.x;
    __shared__ float red[192];
    float v = w[c];
    red[c] = v * v;
    __syncthreads();
    if (c < 64) red[c] += red[c + 64] + red[c + 128];
    __syncthreads();
    if (c < 32) {
        float s = red[c] + red[c + 32];
        for (int o = 16; o; o >>= 1) s += __shfl_down_sync(0xffffffffu, s, o);
        if (c == 0) *outp = sqrtf(s);
    }
}

// ---------------- pooling scores: tanh(x.w / ||w||) ----------------
__global__ void k_scores(const float* __restrict__ xn, const float* __restrict__ w,
                         const float* __restrict__ nrm, float* __restrict__ s) {
    int gw = (blockIdx.x << 3) + (threadIdx.x >> 5);
    int lane = threadIdx.x & 31;
    const float* row = xn + (size_t)gw * CC;
    float acc = 0.f;
#pragma unroll
    for (int c = lane; c < CC; c += 32) acc += row[c] * w[c];
    for (int o = 16; o; o >>= 1) acc += __shfl_down_sync(0xffffffffu, acc, o);
    if (!lane) s[gw] = tanhf(acc / nrm[0]);
}

// ---------------- stable bitonic sort: (score desc, idx asc) ----------------
__global__ void k_sort(const float* __restrict__ s, int* __restrict__ perm,
                       float* __restrict__ sv, int N, int KEEP) {
    extern __shared__ unsigned long long key[];
    int b = blockIdx.x, tid = threadIdx.x, nt = blockDim.x;
    for (int i = tid; i < N; i += nt) {
        unsigned u = __float_as_uint(s[b * N + i]);
        u = (u & 0x80000000u) ? ~u : (u | 0x80000000u);  // monotone ascending map
        u = ~u;                                          // descending by score
        key[i] = ((unsigned long long)u << 32) | (unsigned)i;
    }
    __syncthreads();
    for (int k2 = 2; k2 <= N; k2 <<= 1) {
        for (int j = k2 >> 1; j > 0; j >>= 1) {
            for (int i = tid; i < N; i += nt) {
                int ixj = i ^ j;
                if (ixj > i) {
                    unsigned long long a = key[i], c = key[ixj];
                    bool up = ((i & k2) == 0);
                    if ((a > c) == up) { key[i] = c; key[ixj] = a; }
                }
            }
            __syncthreads();
        }
    }
    for (int i = tid; i < KEEP; i += nt) {
        unsigned long long a = key[i];
        unsigned idx = (unsigned)(a & 0xffffffffu);
        unsigned u = ~(unsigned)(a >> 32);
        u = (u & 0x80000000u) ? (u & 0x7fffffffu) : ~u;  // invert map
        perm[b * KEEP + i] = (int)idx;
        sv[b * KEEP + i] = __uint_as_float(u);
    }
}

// ---------------- gather kept nodes, gate by score ----------------
__global__ void k_gatherpool(const float* __restrict__ in, const int* __restrict__ perm,
                             const float* __restrict__ sv, float* __restrict__ out,
                             int N, int KEEP) {
    int i = blockIdx.x, b = blockIdx.y, c = threadIdx.x;
    int p = perm[b * KEEP + i];
    float g = sv[b * KEEP + i];
    out[((size_t)b * KEEP + i) * CC + c] = in[((size_t)b * N + p) * CC + c] * g;
}

// ---------------- final NHWC->NCHW writeout ----------------
__global__ void k_final(const float* __restrict__ in, float* __restrict__ out) {
    int n = blockIdx.x, b = blockIdx.y, c = threadIdx.x;
    int y = n >> 4, xw = n & 15;
    out[(((size_t)b * CC + c) * 16 + y) * 16 + xw] = in[((size_t)b * 256 + n) * CC + c];
}

// ---------------- launch ----------------
extern "C" void kernel_launch(void* const* d_in, const int* in_sizes, int n_in,
                              void* d_out, int out_size) {
    const float* x     = (const float*)d_in[0];
    const float* W1l   = (const float*)d_in[1];
    const float* b1l   = (const float*)d_in[2];
    const float* W1r   = (const float*)d_in[3];
    const float* p1w   = (const float*)d_in[4];
    const float* gbeta = (const float*)d_in[5];
    const float* ggam  = (const float*)d_in[6];
    const float* W2l   = (const float*)d_in[7];
    const float* b2l   = (const float*)d_in[8];
    const float* W2r   = (const float*)d_in[9];
    const float* p2w   = (const float*)d_in[10];
    float* out = (float*)d_out;

    float *xn, *nb, *sg, *pl, *gd, *sg2, *pl2, *sqn, *sv, *sc, *scal;
    int *idx, *perm;
    cudaGetSymbolAddress((void**)&xn,   g_xn);
    cudaGetSymbolAddress((void**)&nb,   g_nb);
    cudaGetSymbolAddress((void**)&sg,   g_sage);
    cudaGetSymbolAddress((void**)&pl,   g_pool);
    cudaGetSymbolAddress((void**)&gd,   g_gdn);
    cudaGetSymbolAddress((void**)&sg2,  g_sage2);
    cudaGetSymbolAddress((void**)&pl2,  g_pool2);
    cudaGetSymbolAddress((void**)&sqn,  g_sqn);
    cudaGetSymbolAddress((void**)&sv,   g_sv);
    cudaGetSymbolAddress((void**)&sc,   g_scores);
    cudaGetSymbolAddress((void**)&scal, g_scal);
    cudaGetSymbolAddress((void**)&idx,  g_idx);
    cudaGetSymbolAddress((void**)&perm, g_perm);

    k_freq<<<1, 64>>>();

    // ---- stage 1 (N = 4096) ----
    k_prep<<<dim3(NB1, 4), 192>>>(x, xn, sqn);
    k_knn<<<dim3(NB1 / 64, 4), 256>>>(xn, sqn, idx, NB1);
    k_gather<<<dim3(NB1, 4), 192>>>(xn, idx, nb, NB1);
    k_sage<<<dim3(4 * NB1 / 64, 3), 256>>>(nb, xn, W1l, W1r, b1l, sg);
    k_wnorm<<<1, 192>>>(p1w, scal);
    k_scores<<<4 * NB1 / 8, 256>>>(sg, p1w, scal, sc);
    k_sort<<<4, 1024, NB1 * 8>>>(sc, perm, sv, NB1, NB2);
    k_gatherpool<<<dim3(NB2, 4), 192>>>(sg, perm, sv, pl, NB1, NB2);
    k_gdn<<<dim3(4 * NB2 / 64, 3), 256>>>(pl, ggam, gbeta, gd);

    // ---- stage 2 (N = 1024) ----
    k_sqn<<<dim3(NB2, 4), 192>>>(gd, sqn, NB2);
    k_knn<<<dim3(NB2 / 64, 4), 256>>>(gd, sqn, idx, NB2);
    k_gather<<<dim3(NB2, 4), 192>>>(gd, idx, nb, NB2);
    k_sage<<<dim3(4 * NB2 / 64, 3), 256>>>(nb, gd, W2l, W2r, b2l, sg2);
    k_wnorm<<<1, 192>>>(p2w, scal + 1);
    k_scores<<<4 * NB2 / 8, 256>>>(sg2, p2w, scal + 1, sc);
    k_sort<<<4, 1024, NB2 * 8>>>(sc, perm, sv, NB2, 256);
    k_gatherpool<<<dim3(256, 4), 192>>>(sg2, perm, sv, pl2, NB2, 256);
    k_final<<<dim3(256, 4), 192>>>(pl2, out);
}

// round 2
// speedup vs baseline: 1.2947x; 1.2947x over previous
#include <cuda_runtime.h>
#include <math.h>

#define CC 192
#define NB1 4096
#define NB2 1024

// ---------------- scratch (device globals; no allocation) ----------------
__device__ float d_freq[48];
__device__ float g_xn[4 * NB1 * CC];
__device__ float g_nb[4 * NB1 * CC];
__device__ float g_sage[4 * NB1 * CC];
__device__ float g_pool[4 * NB2 * CC];
__device__ float g_gdn[4 * NB2 * CC];
__device__ float g_sage2[4 * NB2 * CC];
__device__ float g_pool2[4 * 256 * CC];
__device__ float g_sqn[4 * NB1];
__device__ int   g_idx[4 * NB1 * 9];
__device__ int   g_perm[4 * NB2];
__device__ float g_sv[4 * NB2];
__device__ float g_scores[4 * NB1];
__device__ float g_scal[2];

// ---------------- packed f32x2 helpers ----------------
__device__ __forceinline__ unsigned long long pk2(float x, float y) {
    unsigned long long r;
    asm("mov.b64 %0, {%1, %2};" : "=l"(r) : "f"(x), "f"(y));
    return r;
}
__device__ __forceinline__ void upk2(unsigned long long v, float& x, float& y) {
    asm("mov.b64 {%0, %1}, %2;" : "=f"(x), "=f"(y) : "l"(v));
}
__device__ __forceinline__ void fma2(unsigned long long& d, unsigned long long a,
                                     unsigned long long b) {
    asm("fma.rn.f32x2 %0, %1, %2, %0;" : "+l"(d) : "l"(a), "l"(b));
}

// ---------------- positional-encoding frequency table ----------------
__global__ void k_freq() {
    int j = threadIdx.x;
    if (j < 48) d_freq[j] = (float)(1.0 / pow(10000.0, (double)(2 * j) / 96.0));
}

// ---------------- add pos-enc, build node features + sq norms ----------------
__global__ void k_prep(const float* __restrict__ x, float* __restrict__ xn,
                       float* __restrict__ sqn) {
    int n = blockIdx.x, b = blockIdx.y, c = threadIdx.x;
    int y = n >> 6, xw = n & 63;
    float v = x[(((size_t)b * CC + c) * 64 + y) * 64 + xw];
    float f, arg;
    if (c < 96) { f = d_freq[c >> 1];        arg = (float)y  * f; }
    else        { f = d_freq[(c - 96) >> 1]; arg = (float)xw * f; }
    v += (c & 1) ? cosf(arg) : sinf(arg);
    xn[((size_t)b * NB1 + n) * CC + c] = v;

    __shared__ float red[192];
    red[c] = v * v;
    __syncthreads();
    if (c < 64) red[c] += red[c + 64] + red[c + 128];
    __syncthreads();
    if (c < 32) {
        float s = red[c] + red[c + 32];
        for (int o = 16; o; o >>= 1) s += __shfl_down_sync(0xffffffffu, s, o);
        if (c == 0) sqn[b * NB1 + n] = s;
    }
}

// ---------------- generic squared-norm kernel ----------------
__global__ void k_sqn(const float* __restrict__ xn, float* __restrict__ sqn, int N) {
    int n = blockIdx.x, b = blockIdx.y, c = threadIdx.x;
    float v = xn[((size_t)b * N + n) * CC + c];
    __shared__ float red[192];
    red[c] = v * v;
    __syncthreads();
    if (c < 64) red[c] += red[c + 64] + red[c + 128];
    __syncthreads();
    if (c < 32) {
        float s = red[c] + red[c + 32];
        for (int o = 16; o; o >>= 1) s += __shfl_down_sync(0xffffffffu, s, o);
        if (c == 0) sqn[b * N + n] = s;
    }
}

// ---------------- fused distance-GEMM (f32x2) + running top-9 ----------------
// 256 threads = 16x16; microtile MR x 8; tile TR x 128; A resident in smem.
template<int MR>
__global__ void k_knn2(const float* __restrict__ xn, const float* __restrict__ sqn,
                       int* __restrict__ idxOut, int N) {
    constexpr int TR    = MR * 16;       // rows per block
    constexpr int APAD  = TR + 8;        // A k-stride (multiple of 4)
    constexpr int SPLIT = 256 / TR;      // threads per row in scan phase
    constexpr int W     = 128 / SPLIT;   // columns scanned per thread per tile

    extern __shared__ float sm[];
    float* Asm = sm;                       // [192][APAD]
    float* Bsm = sm + 192 * APAD;          // [2][8][136]
    float* Dsm = Bsm + 2 * 8 * 136;        // [TR][133]

    int b = blockIdx.y;
    int rowBase = blockIdx.x * TR;
    const float* X  = xn  + (size_t)b * N * CC;
    const float* SQ = sqn + (size_t)b * N;

    int tid = threadIdx.x;
    int ty = tid >> 4, tx = tid & 15;

    // ---- load A tile (TR x 192) into smem, k-major ----
    for (int idx = tid; idx < TR * 48; idx += 256) {
        int row = idx / 48, kq = (idx % 48) * 4;
        float4 v = *(const float4*)(X + (size_t)(rowBase + row) * CC + kq);
        Asm[(kq + 0) * APAD + row] = v.x;
        Asm[(kq + 1) * APAD + row] = v.y;
        Asm[(kq + 2) * APAD + row] = v.z;
        Asm[(kq + 3) * APAD + row] = v.w;
    }

    float sr[MR];
#pragma unroll
    for (int i = 0; i < MR; i++) sr[i] = SQ[rowBase + MR * ty + i];

    // top-9 heaps (private, over this thread's column strip)
    float hd[9]; int hi[9];
#pragma unroll
    for (int q = 0; q < 9; q++) { hd[q] = 3.4e38f; hi[q] = 0x7fffffff; }
    int srow = tid / SPLIT, part = tid % SPLIT;
    const int cb0 = part * W;

    int brow = tid >> 1, bk = (tid & 1) * 4;

    unsigned long long acc[MR][4];
#pragma unroll
    for (int i = 0; i < MR; i++)
#pragma unroll
        for (int j = 0; j < 4; j++) acc[i][j] = 0ull;

    for (int colBase = 0; colBase < N; colBase += 128) {
        // ---- GEMM over K=192 in chunks of 8, double-buffered B ----
        float4 bf = *(const float4*)(X + (size_t)(colBase + brow) * CC + bk);
        int buf = 0;
#pragma unroll 1
        for (int kk = 0; kk < 192; kk += 8) {
            float* bd = Bsm + buf * 1088;
            bd[(bk + 0) * 136 + brow] = bf.x;
            bd[(bk + 1) * 136 + brow] = bf.y;
            bd[(bk + 2) * 136 + brow] = bf.z;
            bd[(bk + 3) * 136 + brow] = bf.w;
            __syncthreads();
            if (kk < 184)
                bf = *(const float4*)(X + (size_t)(colBase + brow) * CC + kk + 8 + bk);
            const float* bb_base = Bsm + buf * 1088 + 8 * tx;
#pragma unroll
            for (int k = 0; k < 8; k++) {
                const float* Ak = Asm + (size_t)(kk + k) * APAD + MR * ty;
                float ar[MR];
#pragma unroll
                for (int i = 0; i < MR; i += 4) {
                    float4 v = *(const float4*)(Ak + i);
                    ar[i] = v.x; ar[i + 1] = v.y; ar[i + 2] = v.z; ar[i + 3] = v.w;
                }
                const unsigned long long* bp =
                    (const unsigned long long*)(bb_base + k * 136);
                unsigned long long b0 = bp[0], b1 = bp[1], b2 = bp[2], b3 = bp[3];
#pragma unroll
                for (int i = 0; i < MR; i++) {
                    unsigned long long aa = pk2(ar[i], ar[i]);
                    fma2(acc[i][0], aa, b0); fma2(acc[i][1], aa, b1);
                    fma2(acc[i][2], aa, b2); fma2(acc[i][3], aa, b3);
                }
            }
            buf ^= 1;
        }

        // ---- distances into Dsm ----
        float scv[8];
        {
            float4 s0 = *(const float4*)(SQ + colBase + 8 * tx);
            float4 s1 = *(const float4*)(SQ + colBase + 8 * tx + 4);
            scv[0] = s0.x; scv[1] = s0.y; scv[2] = s0.z; scv[3] = s0.w;
            scv[4] = s1.x; scv[5] = s1.y; scv[6] = s1.z; scv[7] = s1.w;
        }
#pragma unroll
        for (int i = 0; i < MR; i++) {
            float* drow = Dsm + (MR * ty + i) * 133 + 8 * tx;
#pragma unroll
            for (int j = 0; j < 4; j++) {
                float lo, hh;
                upk2(acc[i][j], lo, hh);
                drow[2 * j]     = fmaf(-2.f, lo, sr[i] + scv[2 * j]);
                drow[2 * j + 1] = fmaf(-2.f, hh, sr[i] + scv[2 * j + 1]);
                acc[i][j] = 0ull;
            }
        }
        __syncthreads();

        // ---- scan this tile's strip, maintain top-9 ----
        const float* dsc = Dsm + srow * 133 + cb0;
#pragma unroll 1
        for (int c = 0; c < W; c++) {
            float dval = dsc[c];
            if (dval < hd[8]) {
                hd[8] = dval; hi[8] = colBase + cb0 + c;
#pragma unroll
                for (int q = 8; q > 0; q--) {
                    if (hd[q - 1] > dval) {
                        float td = hd[q - 1]; hd[q - 1] = hd[q]; hd[q] = td;
                        int   ti = hi[q - 1]; hi[q - 1] = hi[q]; hi[q] = ti;
                    } else break;
                }
            }
        }
        __syncthreads();
    }

    // ---- merge SPLIT partial lists per row (lexicographic on (d, idx)) ----
#pragma unroll
    for (int q = 0; q < 9; q++) {
        Dsm[srow * 133 + part * 9 + q]      = hd[q];
        Dsm[srow * 133 + 64 + part * 9 + q] = __int_as_float(hi[q]);
    }
    __syncthreads();
    if (part == 0) {
        int p[SPLIT];
#pragma unroll
        for (int m = 0; m < SPLIT; m++) p[m] = 0;
        size_t ob = ((size_t)b * N + rowBase + srow) * 9;
        for (int q = 0; q < 9; q++) {
            float bd_ = 3.5e38f; int bi = 0x7fffffff, bm = 0;
#pragma unroll
            for (int m = 0; m < SPLIT; m++) {
                if (p[m] < 9) {
                    float dv = Dsm[srow * 133 + m * 9 + p[m]];
                    int   iv = __float_as_int(Dsm[srow * 133 + 64 + m * 9 + p[m]]);
                    if (dv < bd_ || (dv == bd_ && iv < bi)) { bd_ = dv; bi = iv; bm = m; }
                }
            }
            idxOut[ob + q] = bi;
            p[bm]++;
        }
    }
}

// ---------------- gather + mean over 9 neighbors ----------------
__global__ void k_gather(const float* __restrict__ xn, const int* __restrict__ idx,
                         float* __restrict__ out, int N) {
    __shared__ int sid[9];
    int n = blockIdx.x, b = blockIdx.y, c = threadIdx.x;
    if (c < 9) sid[c] = idx[((size_t)b * N + n) * 9 + c];
    __syncthreads();
    const float* X = xn + (size_t)b * N * CC;
    float s = 0.f;
#pragma unroll
    for (int k = 0; k < 9; k++) s += X[(size_t)sid[k] * CC + c];
    out[((size_t)b * N + n) * CC + c] = s / 9.0f;
}

// ---------------- SAGE: out = A1 @ W1^T + A2 @ W2^T + bias ----------------
__global__ void k_sage(const float* __restrict__ A1, const float* __restrict__ A2,
                       const float* __restrict__ W1, const float* __restrict__ W2,
                       const float* __restrict__ bias, float* __restrict__ out) {
    int rowBase = blockIdx.x << 6;
    int oBase   = blockIdx.y << 6;
    __shared__ __align__(16) float A1s[16][68], A2s[16][68], W1s[16][68], W2s[16][68];
    int tid = threadIdx.x, ty = tid >> 4, tx = tid & 15;
    int lr = tid >> 2, lk = (tid & 3) << 2;
    float acc[4][4] = {};
    for (int kk = 0; kk < 192; kk += 16) {
        float4 a1 = *(const float4*)(A1 + (size_t)(rowBase + lr) * CC + kk + lk);
        float4 a2 = *(const float4*)(A2 + (size_t)(rowBase + lr) * CC + kk + lk);
        float4 w1 = *(const float4*)(W1 + (size_t)(oBase + lr) * CC + kk + lk);
        float4 w2 = *(const float4*)(W2 + (size_t)(oBase + lr) * CC + kk + lk);
        __syncthreads();
        A1s[lk+0][lr]=a1.x; A1s[lk+1][lr]=a1.y; A1s[lk+2][lr]=a1.z; A1s[lk+3][lr]=a1.w;
        A2s[lk+0][lr]=a2.x; A2s[lk+1][lr]=a2.y; A2s[lk+2][lr]=a2.z; A2s[lk+3][lr]=a2.w;
        W1s[lk+0][lr]=w1.x; W1s[lk+1][lr]=w1.y; W1s[lk+2][lr]=w1.z; W1s[lk+3][lr]=w1.w;
        W2s[lk+0][lr]=w2.x; W2s[lk+1][lr]=w2.y; W2s[lk+2][lr]=w2.z; W2s[lk+3][lr]=w2.w;
        __syncthreads();
#pragma unroll
        for (int k = 0; k < 16; k++) {
            float4 xa = *(const float4*)&A1s[k][ty << 2];
            float4 xb = *(const float4*)&A2s[k][ty << 2];
            float4 u  = *(const float4*)&W1s[k][tx << 2];
            float4 v  = *(const float4*)&W2s[k][tx << 2];
            acc[0][0] += xa.x*u.x + xb.x*v.x; acc[0][1] += xa.x*u.y + xb.x*v.y;
            acc[0][2] += xa.x*u.z + xb.x*v.z; acc[0][3] += xa.x*u.w + xb.x*v.w;
            acc[1][0] += xa.y*u.x + xb.y*v.x; acc[1][1] += xa.y*u.y + xb.y*v.y;
            acc[1][2] += xa.y*u.z + xb.y*v.z; acc[1][3] += xa.y*u.w + xb.y*v.w;
            acc[2][0] += xa.z*u.x + xb.z*v.x; acc[2][1] += xa.z*u.y + xb.z*v.y;
            acc[2][2] += xa.z*u.z + xb.z*v.z; acc[2][3] += xa.z*u.w + xb.z*v.w;
            acc[3][0] += xa.w*u.x + xb.w*v.x; acc[3][1] += xa.w*u.y + xb.w*v.y;
            acc[3][2] += xa.w*u.z + xb.w*v.z; acc[3][3] += xa.w*u.w + xb.w*v.w;
        }
    }
#pragma unroll
    for (int i = 0; i < 4; i++)
#pragma unroll
        for (int j = 0; j < 4; j++) {
            int oc = oBase + (tx << 2) + j;
            out[(size_t)(rowBase + (ty << 2) + i) * CC + oc] = acc[i][j] + bias[oc];
        }
}

// ---------------- GDN: y = x * rsqrt(x^2 @ gamma^T + beta) ----------------
__global__ void k_gdn(const float* __restrict__ X, const float* __restrict__ gamma,
                      const float* __restrict__ beta, float* __restrict__ out) {
    int rowBase = blockIdx.x << 6;
    int oBase   = blockIdx.y << 6;
    __shared__ __align__(16) float As[16][68], Gs[16][68];
    int tid = threadIdx.x, ty = tid >> 4, tx = tid & 15;
    int lr = tid >> 2, lk = (tid & 3) << 2;
    float acc[4][4] = {};
    for (int kk = 0; kk < 192; kk += 16) {
        float4 a = *(const float4*)(X     + (size_t)(rowBase + lr) * CC + kk + lk);
        float4 g = *(const float4*)(gamma + (size_t)(oBase + lr) * CC + kk + lk);
        __syncthreads();
        As[lk+0][lr]=a.x*a.x; As[lk+1][lr]=a.y*a.y; As[lk+2][lr]=a.z*a.z; As[lk+3][lr]=a.w*a.w;
        Gs[lk+0][lr]=g.x; Gs[lk+1][lr]=g.y; Gs[lk+2][lr]=g.z; Gs[lk+3][lr]=g.w;
        __syncthreads();
#pragma unroll
        for (int k = 0; k < 16; k++) {
            float4 xa = *(const float4*)&As[k][ty << 2];
            float4 u  = *(const float4*)&Gs[k][tx << 2];
            acc[0][0]+=xa.x*u.x; acc[0][1]+=xa.x*u.y; acc[0][2]+=xa.x*u.z; acc[0][3]+=xa.x*u.w;
            acc[1][0]+=xa.y*u.x; acc[1][1]+=xa.y*u.y; acc[1][2]+=xa.y*u.z; acc[1][3]+=xa.y*u.w;
            acc[2][0]+=xa.z*u.x; acc[2][1]+=xa.z*u.y; acc[2][2]+=xa.z*u.z; acc[2][3]+=xa.z*u.w;
            acc[3][0]+=xa.w*u.x; acc[3][1]+=xa.w*u.y; acc[3][2]+=xa.w*u.z; acc[3][3]+=xa.w*u.w;
        }
    }
#pragma unroll
    for (int i = 0; i < 4; i++)
#pragma unroll
        for (int j = 0; j < 4; j++) {
            int oc = oBase + (tx << 2) + j;
            size_t off = (size_t)(rowBase + (ty << 2) + i) * CC + oc;
            float xv = X[off];
            out[off] = xv * rsqrtf(acc[i][j] + beta[oc]);
        }
}

// ---------------- ||w|| ----------------
__global__ void k_wnorm(const float* __restrict__ w, float* __restrict__ outp) {
    int c = threadIdx.x;
    __shared__ float red[192];
    float v = w[c];
    red[c] = v * v;
    __syncthreads();
    if (c < 64) red[c] += red[c + 64] + red[c + 128];
    __syncthreads();
    if (c < 32) {
        float s = red[c] + red[c + 32];
        for (int o = 16; o; o >>= 1) s += __shfl_down_sync(0xffffffffu, s, o);
        if (c == 0) *outp = sqrtf(s);
    }
}

// ---------------- pooling scores: tanh(x.w / ||w||) ----------------
__global__ void k_scores(const float* __restrict__ xn, const float* __restrict__ w,
                         const float* __restrict__ nrm, float* __restrict__ s) {
    int gw = (blockIdx.x << 3) + (threadIdx.x >> 5);
    int lane = threadIdx.x & 31;
    const float* row = xn + (size_t)gw * CC;
    float acc = 0.f;
#pragma unroll
    for (int c = lane; c < CC; c += 32) acc += row[c] * w[c];
    for (int o = 16; o; o >>= 1) acc += __shfl_down_sync(0xffffffffu, acc, o);
    if (!lane) s[gw] = tanhf(acc / nrm[0]);
}

// ---------------- stable bitonic sort: (score desc, idx asc) ----------------
__global__ void k_sort(const float* __restrict__ s, int* __restrict__ perm,
                       float* __restrict__ sv, int N, int KEEP) {
    extern __shared__ unsigned long long key[];
    int b = blockIdx.x, tid = threadIdx.x, nt = blockDim.x;
    for (int i = tid; i < N; i += nt) {
        unsigned u = __float_as_uint(s[b * N + i]);
        u = (u & 0x80000000u) ? ~u : (u | 0x80000000u);
        u = ~u;
        key[i] = ((unsigned long long)u << 32) | (unsigned)i;
    }
    __syncthreads();
    for (int k2 = 2; k2 <= N; k2 <<= 1) {
        for (int j = k2 >> 1; j > 0; j >>= 1) {
            for (int i = tid; i < N; i += nt) {
                int ixj = i ^ j;
                if (ixj > i) {
                    unsigned long long a = key[i], c = key[ixj];
                    bool up = ((i & k2) == 0);
                    if ((a > c) == up) { key[i] = c; key[ixj] = a; }
                }
            }
            __syncthreads();
        }
    }
    for (int i = tid; i < KEEP; i += nt) {
        unsigned long long a = key[i];
        unsigned idx = (unsigned)(a & 0xffffffffu);
        unsigned u = ~(unsigned)(a >> 32);
        u = (u & 0x80000000u) ? (u & 0x7fffffffu) : ~u;
        perm[b * KEEP + i] = (int)idx;
        sv[b * KEEP + i] = __uint_as_float(u);
    }
}

// ---------------- gather kept nodes, gate by score ----------------
__global__ void k_gatherpool(const float* __restrict__ in, const int* __restrict__ perm,
                             const float* __restrict__ sv, float* __restrict__ out,
                             int N, int KEEP) {
    int i = blockIdx.x, b = blockIdx.y, c = threadIdx.x;
    int p = perm[b * KEEP + i];
    float g = sv[b * KEEP + i];
    out[((size_t)b * KEEP + i) * CC + c] = in[((size_t)b * N + p) * CC + c] * g;
}

// ---------------- final NHWC->NCHW writeout ----------------
__global__ void k_final(const float* __restrict__ in, float* __restrict__ out) {
    int n = blockIdx.x, b = blockIdx.y, c = threadIdx.x;
    int y = n >> 4, xw = n & 15;
    out[(((size_t)b * CC + c) * 16 + y) * 16 + xw] = in[((size_t)b * 256 + n) * CC + c];
}

// ---------------- launch ----------------
extern "C" void kernel_launch(void* const* d_in, const int* in_sizes, int n_in,
                              void* d_out, int out_size) {
    const float* x     = (const float*)d_in[0];
    const float* W1l   = (const float*)d_in[1];
    const float* b1l   = (const float*)d_in[2];
    const float* W1r   = (const float*)d_in[3];
    const float* p1w   = (const float*)d_in[4];
    const float* gbeta = (const float*)d_in[5];
    const float* ggam  = (const float*)d_in[6];
    const float* W2l   = (const float*)d_in[7];
    const float* b2l   = (const float*)d_in[8];
    const float* W2r   = (const float*)d_in[9];
    const float* p2w   = (const float*)d_in[10];
    float* out = (float*)d_out;

    float *xn, *nb, *sg, *pl, *gd, *sg2, *pl2, *sqn, *sv, *sc, *scal;
    int *idx, *perm;
    cudaGetSymbolAddress((void**)&xn,   g_xn);
    cudaGetSymbolAddress((void**)&nb,   g_nb);
    cudaGetSymbolAddress((void**)&sg,   g_sage);
    cudaGetSymbolAddress((void**)&pl,   g_pool);
    cudaGetSymbolAddress((void**)&gd,   g_gdn);
    cudaGetSymbolAddress((void**)&sg2,  g_sage2);
    cudaGetSymbolAddress((void**)&pl2,  g_pool2);
    cudaGetSymbolAddress((void**)&sqn,  g_sqn);
    cudaGetSymbolAddress((void**)&sv,   g_sv);
    cudaGetSymbolAddress((void**)&sc,   g_scores);
    cudaGetSymbolAddress((void**)&scal, g_scal);
    cudaGetSymbolAddress((void**)&idx,  g_idx);
    cudaGetSymbolAddress((void**)&perm, g_perm);

    const int SMEM8 = (192 * 136 + 2 * 8 * 136 + 128 * 133) * 4;  // 181248 B
    const int SMEM4 = (192 * 72  + 2 * 8 * 136 + 64  * 133) * 4;  //  98048 B
    cudaFuncSetAttribute(k_knn2<8>, cudaFuncAttributeMaxDynamicSharedMemorySize, SMEM8);
    cudaFuncSetAttribute(k_knn2<4>, cudaFuncAttributeMaxDynamicSharedMemorySize, SMEM4);

    k_freq<<<1, 64>>>();

    // ---- stage 1 (N = 4096) ----
    k_prep<<<dim3(NB1, 4), 192>>>(x, xn, sqn);
    k_knn2<8><<<dim3(NB1 / 128, 4), 256, SMEM8>>>(xn, sqn, idx, NB1);
    k_gather<<<dim3(NB1, 4), 192>>>(xn, idx, nb, NB1);
    k_sage<<<dim3(4 * NB1 / 64, 3), 256>>>(nb, xn, W1l, W1r, b1l, sg);
    k_wnorm<<<1, 192>>>(p1w, scal);
    k_scores<<<4 * NB1 / 8, 256>>>(sg, p1w, scal, sc);
    k_sort<<<4, 1024, NB1 * 8>>>(sc, perm, sv, NB1, NB2);
    k_gatherpool<<<dim3(NB2, 4), 192>>>(sg, perm, sv, pl, NB1, NB2);
    k_gdn<<<dim3(4 * NB2 / 64, 3), 256>>>(pl, ggam, gbeta, gd);

    // ---- stage 2 (N = 1024) ----
    k_sqn<<<dim3(NB2, 4), 192>>>(gd, sqn, NB2);
    k_knn2<4><<<dim3(NB2 / 64, 4), 256, SMEM4>>>(gd, sqn, idx, NB2);
    k_gather<<<dim3(NB2, 4), 192>>>(gd, idx, nb, NB2);
    k_sage<<<dim3(4 * NB2 / 64, 3), 256>>>(nb, gd, W2l, W2r, b2l, sg2);
    k_wnorm<<<1, 192>>>(p2w, scal + 1);
    k_scores<<<4 * NB2 / 8, 256>>>(sg2, p2w, scal + 1, sc);
    k_sort<<<4, 1024, NB2 * 8>>>(sc, perm, sv, NB2, 256);
    k_gatherpool<<<dim3(256, 4), 192>>>(sg2, perm, sv, pl2, NB2, 256);
    k_final<<<dim3(256, 4), 192>>>(pl2, out);
}

// round 3
// speedup vs baseline: 1.2948x; 1.0000x over previous
#include <cuda_runtime.h>
#include <math.h>

#define CC 192
#define NB1 4096
#define NB2 1024

// ---------------- scratch (device globals; no allocation) ----------------
__device__ float d_freq[48];
__device__ float g_xn[4 * NB1 * CC];
__device__ float g_nb[4 * NB1 * CC];
__device__ float g_sage[4 * NB1 * CC];
__device__ float g_pool[4 * NB2 * CC];
__device__ float g_gdn[4 * NB2 * CC];
__device__ float g_sage2[4 * NB2 * CC];
__device__ float g_pool2[4 * 256 * CC];
__device__ float g_sqn[4 * NB1];
__device__ int   g_idx[4 * NB1 * 9];
__device__ int   g_perm[4 * NB2];
__device__ float g_sv[4 * NB2];
__device__ float g_scores[4 * NB1];
__device__ float g_scal[2];

// ---------------- packed f32x2 helpers ----------------
__device__ __forceinline__ unsigned long long pk2(float x, float y) {
    unsigned long long r;
    asm("mov.b64 %0, {%1, %2};" : "=l"(r) : "f"(x), "f"(y));
    return r;
}
__device__ __forceinline__ void upk2(unsigned long long v, float& x, float& y) {
    asm("mov.b64 {%0, %1}, %2;" : "=f"(x), "=f"(y) : "l"(v));
}
__device__ __forceinline__ void fma2(unsigned long long& d, unsigned long long a,
                                     unsigned long long b) {
    asm("fma.rn.f32x2 %0, %1, %2, %0;" : "+l"(d) : "l"(a), "l"(b));
}

// ---------------- positional-encoding frequency table ----------------
__global__ void k_freq() {
    int j = threadIdx.x;
    if (j < 48) d_freq[j] = (float)(1.0 / pow(10000.0, (double)(2 * j) / 96.0));
}

// ---------------- add pos-enc, build node features + sq norms ----------------
__global__ void k_prep(const float* __restrict__ x, float* __restrict__ xn,
                       float* __restrict__ sqn) {
    int n = blockIdx.x, b = blockIdx.y, c = threadIdx.x;
    int y = n >> 6, xw = n & 63;
    float v = x[(((size_t)b * CC + c) * 64 + y) * 64 + xw];
    float f, arg;
    if (c < 96) { f = d_freq[c >> 1];        arg = (float)y  * f; }
    else        { f = d_freq[(c - 96) >> 1]; arg = (float)xw * f; }
    v += (c & 1) ? cosf(arg) : sinf(arg);
    xn[((size_t)b * NB1 + n) * CC + c] = v;

    __shared__ float red[192];
    red[c] = v * v;
    __syncthreads();
    if (c < 64) red[c] += red[c + 64] + red[c + 128];
    __syncthreads();
    if (c < 32) {
        float s = red[c] + red[c + 32];
        for (int o = 16; o; o >>= 1) s += __shfl_down_sync(0xffffffffu, s, o);
        if (c == 0) sqn[b * NB1 + n] = s;
    }
}

// ---------------- generic squared-norm kernel ----------------
__global__ void k_sqn(const float* __restrict__ xn, float* __restrict__ sqn, int N) {
    int n = blockIdx.x, b = blockIdx.y, c = threadIdx.x;
    float v = xn[((size_t)b * N + n) * CC + c];
    __shared__ float red[192];
    red[c] = v * v;
    __syncthreads();
    if (c < 64) red[c] += red[c + 64] + red[c + 128];
    __syncthreads();
    if (c < 32) {
        float s = red[c] + red[c + 32];
        for (int o = 16; o; o >>= 1) s += __shfl_down_sync(0xffffffffu, s, o);
        if (c == 0) sqn[b * N + n] = s;
    }
}

// ---------------- fused distance-GEMM (f32x2) + running top-9 ----------------
// 256 threads = 16x16; microtile MR x 8; tile TR x 128; A resident in smem.
template<int MR>
__global__ void k_knn2(const float* __restrict__ xn, const float* __restrict__ sqn,
                       int* __restrict__ idxOut, int N) {
    constexpr int TR    = MR * 16;       // rows per block
    constexpr int APAD  = TR + 8;        // A k-stride (multiple of 4)
    constexpr int SPLIT = 256 / TR;      // threads per row in scan phase
    constexpr int W     = 128 / SPLIT;   // columns scanned per thread per tile

    extern __shared__ float sm[];
    float* Asm = sm;                       // [192][APAD]
    float* Bsm = sm + 192 * APAD;          // [2][8][136]
    float* Dsm = Bsm + 2 * 8 * 136;        // [TR][133]

    int b = blockIdx.y;
    int rowBase = blockIdx.x * TR;
    const float* X  = xn  + (size_t)b * N * CC;
    const float* SQ = sqn + (size_t)b * N;

    int tid = threadIdx.x;
    int ty = tid >> 4, tx = tid & 15;

    // ---- load A tile (TR x 192) into smem, k-major ----
    for (int idx = tid; idx < TR * 48; idx += 256) {
        int row = idx / 48, kq = (idx % 48) * 4;
        float4 v = *(const float4*)(X + (size_t)(rowBase + row) * CC + kq);
        Asm[(kq + 0) * APAD + row] = v.x;
        Asm[(kq + 1) * APAD + row] = v.y;
        Asm[(kq + 2) * APAD + row] = v.z;
        Asm[(kq + 3) * APAD + row] = v.w;
    }

    float sr[MR];
#pragma unroll
    for (int i = 0; i < MR; i++) sr[i] = SQ[rowBase + MR * ty + i];

    // top-9 heaps (private, over this thread's column strip)
    float hd[9]; int hi[9];
#pragma unroll
    for (int q = 0; q < 9; q++) { hd[q] = 3.4e38f; hi[q] = 0x7fffffff; }
    int srow = tid / SPLIT, part = tid % SPLIT;
    const int cb0 = part * W;

    int brow = tid >> 1, bk = (tid & 1) * 4;

    unsigned long long acc[MR][4];
#pragma unroll
    for (int i = 0; i < MR; i++)
#pragma unroll
        for (int j = 0; j < 4; j++) acc[i][j] = 0ull;

    for (int colBase = 0; colBase < N; colBase += 128) {
        // ---- GEMM over K=192 in chunks of 8, double-buffered B ----
        float4 bf = *(const float4*)(X + (size_t)(colBase + brow) * CC + bk);
        int buf = 0;
#pragma unroll 1
        for (int kk = 0; kk < 192; kk += 8) {
            float* bd = Bsm + buf * 1088;
            bd[(bk + 0) * 136 + brow] = bf.x;
            bd[(bk + 1) * 136 + brow] = bf.y;
            bd[(bk + 2) * 136 + brow] = bf.z;
            bd[(bk + 3) * 136 + brow] = bf.w;
            __syncthreads();
            if (kk < 184)
                bf = *(const float4*)(X + (size_t)(colBase + brow) * CC + kk + 8 + bk);
            const float* bb_base = Bsm + buf * 1088 + 8 * tx;
#pragma unroll
            for (int k = 0; k < 8; k++) {
                const float* Ak = Asm + (size_t)(kk + k) * APAD + MR * ty;
                float ar[MR];
#pragma unroll
                for (int i = 0; i < MR; i += 4) {
                    float4 v = *(const float4*)(Ak + i);
                    ar[i] = v.x; ar[i + 1] = v.y; ar[i + 2] = v.z; ar[i + 3] = v.w;
                }
                const unsigned long long* bp =
                    (const unsigned long long*)(bb_base + k * 136);
                unsigned long long b0 = bp[0], b1 = bp[1], b2 = bp[2], b3 = bp[3];
#pragma unroll
                for (int i = 0; i < MR; i++) {
                    unsigned long long aa = pk2(ar[i], ar[i]);
                    fma2(acc[i][0], aa, b0); fma2(acc[i][1], aa, b1);
                    fma2(acc[i][2], aa, b2); fma2(acc[i][3], aa, b3);
                }
            }
            buf ^= 1;
        }

        // ---- distances into Dsm ----
        float scv[8];
        {
            float4 s0 = *(const float4*)(SQ + colBase + 8 * tx);
            float4 s1 = *(const float4*)(SQ + colBase + 8 * tx + 4);
            scv[0] = s0.x; scv[1] = s0.y; scv[2] = s0.z; scv[3] = s0.w;
            scv[4] = s1.x; scv[5] = s1.y; scv[6] = s1.z; scv[7] = s1.w;
        }
#pragma unroll
        for (int i = 0; i < MR; i++) {
            float* drow = Dsm + (MR * ty + i) * 133 + 8 * tx;
#pragma unroll
            for (int j = 0; j < 4; j++) {
                float lo, hh;
                upk2(acc[i][j], lo, hh);
                drow[2 * j]     = fmaf(-2.f, lo, sr[i] + scv[2 * j]);
                drow[2 * j + 1] = fmaf(-2.f, hh, sr[i] + scv[2 * j + 1]);
                acc[i][j] = 0ull;
            }
        }
        __syncthreads();

        // ---- scan this tile's strip, maintain top-9 ----
        const float* dsc = Dsm + srow * 133 + cb0;
#pragma unroll 1
        for (int c = 0; c < W; c++) {
            float dval = dsc[c];
            if (dval < hd[8]) {
                hd[8] = dval; hi[8] = colBase + cb0 + c;
#pragma unroll
                for (int q = 8; q > 0; q--) {
                    if (hd[q - 1] > dval) {
                        float td = hd[q - 1]; hd[q - 1] = hd[q]; hd[q] = td;
                        int   ti = hi[q - 1]; hi[q - 1] = hi[q]; hi[q] = ti;
                    } else break;
                }
            }
        }
        __syncthreads();
    }

    // ---- merge SPLIT partial lists per row (lexicographic on (d, idx)) ----
#pragma unroll
    for (int q = 0; q < 9; q++) {
        Dsm[srow * 133 + part * 9 + q]      = hd[q];
        Dsm[srow * 133 + 64 + part * 9 + q] = __int_as_float(hi[q]);
    }
    __syncthreads();
    if (part == 0) {
        int p[SPLIT];
#pragma unroll
        for (int m = 0; m < SPLIT; m++) p[m] = 0;
        size_t ob = ((size_t)b * N + rowBase + srow) * 9;
        for (int q = 0; q < 9; q++) {
            float bd_ = 3.5e38f; int bi = 0x7fffffff, bm = 0;
#pragma unroll
            for (int m = 0; m < SPLIT; m++) {
                if (p[m] < 9) {
                    float dv = Dsm[srow * 133 + m * 9 + p[m]];
                    int   iv = __float_as_int(Dsm[srow * 133 + 64 + m * 9 + p[m]]);
                    if (dv < bd_ || (dv == bd_ && iv < bi)) { bd_ = dv; bi = iv; bm = m; }
                }
            }
            idxOut[ob + q] = bi;
            p[bm]++;
        }
    }
}

// ---------------- gather + mean over 9 neighbors ----------------
__global__ void k_gather(const float* __restrict__ xn, const int* __restrict__ idx,
                         float* __restrict__ out, int N) {
    __shared__ int sid[9];
    int n = blockIdx.x, b = blockIdx.y, c = threadIdx.x;
    if (c < 9) sid[c] = idx[((size_t)b * N + n) * 9 + c];
    __syncthreads();
    const float* X = xn + (size_t)b * N * CC;
    float s = 0.f;
#pragma unroll
    for (int k = 0; k < 9; k++) s += X[(size_t)sid[k] * CC + c];
    out[((size_t)b * N + n) * CC + c] = s / 9.0f;
}

// ---------------- SAGE: out = A1 @ W1^T + A2 @ W2^T + bias ----------------
__global__ void k_sage(const float* __restrict__ A1, const float* __restrict__ A2,
                       const float* __restrict__ W1, const float* __restrict__ W2,
                       const float* __restrict__ bias, float* __restrict__ out) {
    int rowBase = blockIdx.x << 6;
    int oBase   = blockIdx.y << 6;
    __shared__ __align__(16) float A1s[16][68], A2s[16][68], W1s[16][68], W2s[16][68];
    int tid = threadIdx.x, ty = tid >> 4, tx = tid & 15;
    int lr = tid >> 2, lk = (tid & 3) << 2;
    float acc[4][4] = {};
    for (int kk = 0; kk < 192; kk += 16) {
        float4 a1 = *(const float4*)(A1 + (size_t)(rowBase + lr) * CC + kk + lk);
        float4 a2 = *(const float4*)(A2 + (size_t)(rowBase + lr) * CC + kk + lk);
        float4 w1 = *(const float4*)(W1 + (size_t)(oBase + lr) * CC + kk + lk);
        float4 w2 = *(const float4*)(W2 + (size_t)(oBase + lr) * CC + kk + lk);
        __syncthreads();
        A1s[lk+0][lr]=a1.x; A1s[lk+1][lr]=a1.y; A1s[lk+2][lr]=a1.z; A1s[lk+3][lr]=a1.w;
        A2s[lk+0][lr]=a2.x; A2s[lk+1][lr]=a2.y; A2s[lk+2][lr]=a2.z; A2s[lk+3][lr]=a2.w;
        W1s[lk+0][lr]=w1.x; W1s[lk+1][lr]=w1.y; W1s[lk+2][lr]=w1.z; W1s[lk+3][lr]=w1.w;
        W2s[lk+0][lr]=w2.x; W2s[lk+1][lr]=w2.y; W2s[lk+2][lr]=w2.z; W2s[lk+3][lr]=w2.w;
        __syncthreads();
#pragma unroll
        for (int k = 0; k < 16; k++) {
            float4 xa = *(const float4*)&A1s[k][ty << 2];
            float4 xb = *(const float4*)&A2s[k][ty << 2];
            float4 u  = *(const float4*)&W1s[k][tx << 2];
            float4 v  = *(const float4*)&W2s[k][tx << 2];
            acc[0][0] += xa.x*u.x + xb.x*v.x; acc[0][1] += xa.x*u.y + xb.x*v.y;
            acc[0][2] += xa.x*u.z + xb.x*v.z; acc[0][3] += xa.x*u.w + xb.x*v.w;
            acc[1][0] += xa.y*u.x + xb.y*v.x; acc[1][1] += xa.y*u.y + xb.y*v.y;
            acc[1][2] += xa.y*u.z + xb.y*v.z; acc[1][3] += xa.y*u.w + xb.y*v.w;
            acc[2][0] += xa.z*u.x + xb.z*v.x; acc[2][1] += xa.z*u.y + xb.z*v.y;
            acc[2][2] += xa.z*u.z + xb.z*v.z; acc[2][3] += xa.z*u.w + xb.z*v.w;
            acc[3][0] += xa.w*u.x + xb.w*v.x; acc[3][1] += xa.w*u.y + xb.w*v.y;
            acc[3][2] += xa.w*u.z + xb.w*v.z; acc[3][3] += xa.w*u.w + xb.w*v.w;
        }
    }
#pragma unroll
    for (int i = 0; i < 4; i++)
#pragma unroll
        for (int j = 0; j < 4; j++) {
            int oc = oBase + (tx << 2) + j;
            out[(size_t)(rowBase + (ty << 2) + i) * CC + oc] = acc[i][j] + bias[oc];
        }
}

// ---------------- GDN: y = x * rsqrt(x^2 @ gamma^T + beta) ----------------
__global__ void k_gdn(const float* __restrict__ X, const float* __restrict__ gamma,
                      const float* __restrict__ beta, float* __restrict__ out) {
    int rowBase = blockIdx.x << 6;
    int oBase   = blockIdx.y << 6;
    __shared__ __align__(16) float As[16][68], Gs[16][68];
    int tid = threadIdx.x, ty = tid >> 4, tx = tid & 15;
    int lr = tid >> 2, lk = (tid & 3) << 2;
    float acc[4][4] = {};
    for (int kk = 0; kk < 192; kk += 16) {
        float4 a = *(const float4*)(X     + (size_t)(rowBase + lr) * CC + kk + lk);
        float4 g = *(const float4*)(gamma + (size_t)(oBase + lr) * CC + kk + lk);
        __syncthreads();
        As[lk+0][lr]=a.x*a.x; As[lk+1][lr]=a.y*a.y; As[lk+2][lr]=a.z*a.z; As[lk+3][lr]=a.w*a.w;
        Gs[lk+0][lr]=g.x; Gs[lk+1][lr]=g.y; Gs[lk+2][lr]=g.z; Gs[lk+3][lr]=g.w;
        __syncthreads();
#pragma unroll
        for (int k = 0; k < 16; k++) {
            float4 xa = *(const float4*)&As[k][ty << 2];
            float4 u  = *(const float4*)&Gs[k][tx << 2];
            acc[0][0]+=xa.x*u.x; acc[0][1]+=xa.x*u.y; acc[0][2]+=xa.x*u.z; acc[0][3]+=xa.x*u.w;
            acc[1][0]+=xa.y*u.x; acc[1][1]+=xa.y*u.y; acc[1][2]+=xa.y*u.z; acc[1][3]+=xa.y*u.w;
            acc[2][0]+=xa.z*u.x; acc[2][1]+=xa.z*u.y; acc[2][2]+=xa.z*u.z; acc[2][3]+=xa.z*u.w;
            acc[3][0]+=xa.w*u.x; acc[3][1]+=xa.w*u.y; acc[3][2]+=xa.w*u.z; acc[3][3]+=xa.w*u.w;
        }
    }
#pragma unroll
    for (int i = 0; i < 4; i++)
#pragma unroll
        for (int j = 0; j < 4; j++) {
            int oc = oBase + (tx << 2) + j;
            size_t off = (size_t)(rowBase + (ty << 2) + i) * CC + oc;
            float xv = X[off];
            out[off] = xv * rsqrtf(acc[i][j] + beta[oc]);
        }
}

// ---------------- ||w|| ----------------
__global__ void k_wnorm(const float* __restrict__ w, float* __restrict__ outp) {
    int c = threadIdx.x;
    __shared__ float red[192];
    float v = w[c];
    red[c] = v * v;
    __syncthreads();
    if (c < 64) red[c] += red[c + 64] + red[c + 128];
    __syncthreads();
    if (c < 32) {
        float s = red[c] + red[c + 32];
        for (int o = 16; o; o >>= 1) s += __shfl_down_sync(0xffffffffu, s, o);
        if (c == 0) *outp = sqrtf(s);
    }
}

// ---------------- pooling scores: tanh(x.w / ||w||) ----------------
__global__ void k_scores(const float* __restrict__ xn, const float* __restrict__ w,
                         const float* __restrict__ nrm, float* __restrict__ s) {
    int gw = (blockIdx.x << 3) + (threadIdx.x >> 5);
    int lane = threadIdx.x & 31;
    const float* row = xn + (size_t)gw * CC;
    float acc = 0.f;
#pragma unroll
    for (int c = lane; c < CC; c += 32) acc += row[c] * w[c];
    for (int o = 16; o; o >>= 1) acc += __shfl_down_sync(0xffffffffu, acc, o);
    if (!lane) s[gw] = tanhf(acc / nrm[0]);
}

// ---------------- stable bitonic sort: (score desc, idx asc) ----------------
__global__ void k_sort(const float* __restrict__ s, int* __restrict__ perm,
                       float* __restrict__ sv, int N, int KEEP) {
    extern __shared__ unsigned long long key[];
    int b = blockIdx.x, tid = threadIdx.x, nt = blockDim.x;
    for (int i = tid; i < N; i += nt) {
        unsigned u = __float_as_uint(s[b * N + i]);
        u = (u & 0x80000000u) ? ~u : (u | 0x80000000u);
        u = ~u;
        key[i] = ((unsigned long long)u << 32) | (unsigned)i;
    }
    __syncthreads();
    for (int k2 = 2; k2 <= N; k2 <<= 1) {
        for (int j = k2 >> 1; j > 0; j >>= 1) {
            for (int i = tid; i < N; i += nt) {
                int ixj = i ^ j;
                if (ixj > i) {
                    unsigned long long a = key[i], c = key[ixj];
                    bool up = ((i & k2) == 0);
                    if ((a > c) == up) { key[i] = c; key[ixj] = a; }
                }
            }
            __syncthreads();
        }
    }
    for (int i = tid; i < KEEP; i += nt) {
        unsigned long long a = key[i];
        unsigned idx = (unsigned)(a & 0xffffffffu);
        unsigned u = ~(unsigned)(a >> 32);
        u = (u & 0x80000000u) ? (u & 0x7fffffffu) : ~u;
        perm[b * KEEP + i] = (int)idx;
        sv[b * KEEP + i] = __uint_as_float(u);
    }
}

// ---------------- gather kept nodes, gate by score ----------------
__global__ void k_gatherpool(const float* __restrict__ in, const int* __restrict__ perm,
                             const float* __restrict__ sv, float* __restrict__ out,
                             int N, int KEEP) {
    int i = blockIdx.x, b = blockIdx.y, c = threadIdx.x;
    int p = perm[b * KEEP + i];
    float g = sv[b * KEEP + i];
    out[((size_t)b * KEEP + i) * CC + c] = in[((size_t)b * N + p) * CC + c] * g;
}

// ---------------- final NHWC->NCHW writeout ----------------
__global__ void k_final(const float* __restrict__ in, float* __restrict__ out) {
    int n = blockIdx.x, b = blockIdx.y, c = threadIdx.x;
    int y = n >> 4, xw = n & 15;
    out[(((size_t)b * CC + c) * 16 + y) * 16 + xw] = in[((size_t)b * 256 + n) * CC + c];
}

// ---------------- launch ----------------
extern "C" void kernel_launch(void* const* d_in, const int* in_sizes, int n_in,
                              void* d_out, int out_size) {
    const float* x     = (const float*)d_in[0];
    const float* W1l   = (const float*)d_in[1];
    const float* b1l   = (const float*)d_in[2];
    const float* W1r   = (const float*)d_in[3];
    const float* p1w   = (const float*)d_in[4];
    const float* gbeta = (const float*)d_in[5];
    const float* ggam  = (const float*)d_in[6];
    const float* W2l   = (const float*)d_in[7];
    const float* b2l   = (const float*)d_in[8];
    const float* W2r   = (const float*)d_in[9];
    const float* p2w   = (const float*)d_in[10];
    float* out = (float*)d_out;

    float *xn, *nb, *sg, *pl, *gd, *sg2, *pl2, *sqn, *sv, *sc, *scal;
    int *idx, *perm;
    cudaGetSymbolAddress((void**)&xn,   g_xn);
    cudaGetSymbolAddress((void**)&nb,   g_nb);
    cudaGetSymbolAddress((void**)&sg,   g_sage);
    cudaGetSymbolAddress((void**)&pl,   g_pool);
    cudaGetSymbolAddress((void**)&gd,   g_gdn);
    cudaGetSymbolAddress((void**)&sg2,  g_sage2);
    cudaGetSymbolAddress((void**)&pl2,  g_pool2);
    cudaGetSymbolAddress((void**)&sqn,  g_sqn);
    cudaGetSymbolAddress((void**)&sv,   g_sv);
    cudaGetSymbolAddress((void**)&sc,   g_scores);
    cudaGetSymbolAddress((void**)&scal, g_scal);
    cudaGetSymbolAddress((void**)&idx,  g_idx);
    cudaGetSymbolAddress((void**)&perm, g_perm);

    const int SMEM8 = (192 * 136 + 2 * 8 * 136 + 128 * 133) * 4;  // 181248 B
    const int SMEM4 = (192 * 72  + 2 * 8 * 136 + 64  * 133) * 4;  //  98048 B
    cudaFuncSetAttribute(k_knn2<8>, cudaFuncAttributeMaxDynamicSharedMemorySize, SMEM8);
    cudaFuncSetAttribute(k_knn2<4>, cudaFuncAttributeMaxDynamicSharedMemorySize, SMEM4);

    k_freq<<<1, 64>>>();

    // ---- stage 1 (N = 4096) ----
    k_prep<<<dim3(NB1, 4), 192>>>(x, xn, sqn);
    k_knn2<8><<<dim3(NB1 / 128, 4), 256, SMEM8>>>(xn, sqn, idx, NB1);
    k_gather<<<dim3(NB1, 4), 192>>>(xn, idx, nb, NB1);
    k_sage<<<dim3(4 * NB1 / 64, 3), 256>>>(nb, xn, W1l, W1r, b1l, sg);
    k_wnorm<<<1, 192>>>(p1w, scal);
    k_scores<<<4 * NB1 / 8, 256>>>(sg, p1w, scal, sc);
    k_sort<<<4, 1024, NB1 * 8>>>(sc, perm, sv, NB1, NB2);
    k_gatherpool<<<dim3(NB2, 4), 192>>>(sg, perm, sv, pl, NB1, NB2);
    k_gdn<<<dim3(4 * NB2 / 64, 3), 256>>>(pl, ggam, gbeta, gd);

    // ---- stage 2 (N = 1024) ----
    k_sqn<<<dim3(NB2, 4), 192>>>(gd, sqn, NB2);
    k_knn2<4><<<dim3(NB2 / 64, 4), 256, SMEM4>>>(gd, sqn, idx, NB2);
    k_gather<<<dim3(NB2, 4), 192>>>(gd, idx, nb, NB2);
    k_sage<<<dim3(4 * NB2 / 64, 3), 256>>>(nb, gd, W2l, W2r, b2l, sg2);
    k_wnorm<<<1, 192>>>(p2w, scal + 1);
    k_scores<<<4 * NB2 / 8, 256>>>(sg2, p2w, scal + 1, sc);
    k_sort<<<4, 1024, NB2 * 8>>>(sc, perm, sv, NB2, 256);
    k_gatherpool<<<dim3(256, 4), 192>>>(sg2, perm, sv, pl2, NB2, 256);
    k_final<<<dim3(256, 4), 192>>>(pl2, out);
}